// round 3
// baseline (speedup 1.0000x reference)
#include <cuda_runtime.h>

#define RANK 53
#define CIN  32
#define COUT 64
#define DIM  56
#define NVOX (56*56*56)   // 175616
#define STRH (56*56)
#define STRW 56
#define TH 8
#define TW 8
#define VOXT 128          // voxels per GEMM block tile (NVOX/VOXT = 1372 exact)

// Scratch: two rank-major intermediates [RANK][NVOX] (~35.5 MB each).
__device__ float g_bufA[RANK * NVOX];
__device__ float g_bufB[RANK * NVOX];

// ---------- packed f32x2 helpers (sm_103a) ----------
__device__ __forceinline__ unsigned long long pk2(float lo, float hi) {
    unsigned long long r;
    asm("mov.b64 %0, {%1, %2};" : "=l"(r) : "f"(lo), "f"(hi));
    return r;
}
__device__ __forceinline__ unsigned long long fma2(unsigned long long a,
                                                   unsigned long long b,
                                                   unsigned long long c) {
    unsigned long long d;
    asm("fma.rn.f32x2 %0, %1, %2, %3;" : "=l"(d) : "l"(a), "l"(b), "l"(c));
    return d;
}

// ---------- Kernel 1: pointwise Cin -> RANK, register-tiled GEMM ----------
// bufA[r][v] = sum_c Ucin[c][r] * x[c][v]
__global__ __launch_bounds__(128, 4)
void k_pointwise(const float* __restrict__ x, const float* __restrict__ Ucin) {
    __shared__ float x_s[CIN * VOXT];                    // 16 KB
    __shared__ unsigned long long w_s[CIN * 64];         // 16 KB (rank padded to 64)

    const int tid = threadIdx.x;
    const int vbase = blockIdx.x * VOXT;

    for (int i = tid; i < CIN * 64; i += 128) {
        int c = i >> 6, r = i & 63;
        float v = (r < RANK) ? Ucin[c * RANK + r] : 0.f;
        w_s[i] = pk2(v, v);
    }
    for (int i = tid; i < CIN * (VOXT / 4); i += 128) {
        int c = i >> 5, q = i & 31;
        *(float4*)(x_s + c * VOXT + q * 4) =
            *(const float4*)(x + (size_t)c * NVOX + vbase + q * 4);
    }
    __syncthreads();

    const int r0 = (tid & 7) * 8;
    const int v0 = (tid >> 3) * 8;

    unsigned long long acc[8][4];
#pragma unroll
    for (int i = 0; i < 8; i++)
#pragma unroll
        for (int k = 0; k < 4; k++) acc[i][k] = 0ull;

#pragma unroll 2
    for (int c = 0; c < CIN; c++) {
        ulonglong2 wv0 = *(const ulonglong2*)(w_s + c * 64 + r0);
        ulonglong2 wv1 = *(const ulonglong2*)(w_s + c * 64 + r0 + 2);
        ulonglong2 wv2 = *(const ulonglong2*)(w_s + c * 64 + r0 + 4);
        ulonglong2 wv3 = *(const ulonglong2*)(w_s + c * 64 + r0 + 6);
        ulonglong2 xa  = *(const ulonglong2*)(x_s + c * VOXT + v0);
        ulonglong2 xb  = *(const ulonglong2*)(x_s + c * VOXT + v0 + 4);
        unsigned long long w[8] = {wv0.x, wv0.y, wv1.x, wv1.y, wv2.x, wv2.y, wv3.x, wv3.y};
        unsigned long long xx[4] = {xa.x, xa.y, xb.x, xb.y};
#pragma unroll
        for (int i = 0; i < 8; i++)
#pragma unroll
            for (int k = 0; k < 4; k++)
                acc[i][k] = fma2(w[i], xx[k], acc[i][k]);
    }

#pragma unroll
    for (int i = 0; i < 8; i++) {
        int r = r0 + i;
        if (r < RANK) {
            float* o = g_bufA + (size_t)r * NVOX + vbase + v0;
            *(ulonglong2*)(o)     = make_ulonglong2(acc[i][0], acc[i][1]);
            *(ulonglong2*)(o + 4) = make_ulonglong2(acc[i][2], acc[i][3]);
        }
    }
}

// ---------- Kernel 2: fused H+W 3-tap separable conv, smem tiled ----------
__global__ __launch_bounds__(128)
void k_convHW(const float* __restrict__ in, float* __restrict__ out,
              const float* __restrict__ Ukh, const float* __restrict__ Ukw) {
    __shared__ float s[(TH + 2) * (TW + 2) * DIM];   // 22.4 KB

    int r  = blockIdx.z;
    int h0 = blockIdx.y * TH;
    int w0 = blockIdx.x * TW;
    const float* base = in + (size_t)r * NVOX;

    const int NLOAD4 = (TH + 2) * (TW + 2) * (DIM / 4);
    for (int i = threadIdx.x; i < NLOAD4; i += 128) {
        int dq = i % (DIM / 4);
        int t  = i / (DIM / 4);
        int lw = t % (TW + 2);
        int lh = t / (TW + 2);
        int gh = h0 + lh - 1, gw = w0 + lw - 1;
        float4 val = make_float4(0.f, 0.f, 0.f, 0.f);
        if (gh >= 0 && gh < DIM && gw >= 0 && gw < DIM)
            val = *(const float4*)(base + gh * STRH + gw * STRW + dq * 4);
        *(float4*)(s + (lh * (TW + 2) + lw) * DIM + dq * 4) = val;
    }
    __syncthreads();

    float kh[3] = {Ukh[r], Ukh[RANK + r], Ukh[2 * RANK + r]};
    float kw[3] = {Ukw[r], Ukw[RANK + r], Ukw[2 * RANK + r]};
    float kk[9];
#pragma unroll
    for (int i = 0; i < 3; i++)
#pragma unroll
        for (int j = 0; j < 3; j++) kk[i * 3 + j] = kh[i] * kw[j];

    float* obase = out + (size_t)r * NVOX;
    const int NOUT4 = TH * TW * (DIM / 4);
    for (int o = threadIdx.x; o < NOUT4; o += 128) {
        int dq = o % (DIM / 4);
        int t  = o / (DIM / 4);
        int lw = t % TW;
        int lh = t / TW;
        float4 acc = make_float4(0.f, 0.f, 0.f, 0.f);
#pragma unroll
        for (int i = 0; i < 3; i++)
#pragma unroll
            for (int j = 0; j < 3; j++) {
                const float4 v = *(const float4*)(s + ((lh + i) * (TW + 2) + (lw + j)) * DIM + dq * 4);
                float c = kk[i * 3 + j];
                acc.x += c * v.x; acc.y += c * v.y;
                acc.z += c * v.z; acc.w += c * v.w;
            }
        *(float4*)(obase + (h0 + lh) * STRH + (w0 + lw) * STRW + dq * 4) = acc;
    }
}

// ---------- Kernel 3: fused depth conv + full projection RANK -> 64, GEMM-tiled ----------
// Dynamic smem layout (bytes):
//   t_s   float[53][128]              [0, 27136)
//   w_s   u64  [53][64]               [27136, 54272)
//   kd_s  float[3][53]                [54272, 54908)
//   b_s   float[64]                   [54908, 55164)
#define DPROJ_SMEM 55168
__global__ __launch_bounds__(128, 4)
void k_dproj(const float* __restrict__ in, const float* __restrict__ Ukd,
             const float* __restrict__ Ucout, const float* __restrict__ bias,
             float* __restrict__ out) {
    extern __shared__ char dsm[];
    float* t_s = (float*)dsm;
    unsigned long long* w_s = (unsigned long long*)(dsm + 27136);
    float* kd_s = (float*)(dsm + 54272);
    float* b_s  = (float*)(dsm + 54908);

    const int tid = threadIdx.x;
    const int vbase = blockIdx.x * VOXT;

    // stage weights / kd / bias
    for (int i = tid; i < RANK * COUT; i += 128) {
        float v = Ucout[i];
        w_s[i] = pk2(v, v);
    }
    for (int i = tid; i < 3 * RANK; i += 128) kd_s[i] = Ukd[i];
    if (tid < COUT) b_s[tid] = bias[tid];

    // stage 1: depth conv -> t_s[r][0..127]
    for (int i = tid; i < RANK * (VOXT / 4); i += 128) {
        int r = i >> 5, q = i & 31;
        int v4 = vbase + q * 4;
        int z  = v4 % DIM;                 // always multiple of 4
        const float* p = in + (size_t)r * NVOX + v4;
        float4 c = *(const float4*)p;
        float lf = (z > 0)  ? p[-1] : 0.f;
        float rt = (z < 52) ? p[4]  : 0.f;
        float k0 = kd_s[r], k1 = kd_s[RANK + r], k2 = kd_s[2 * RANK + r];
        float4 t;
        t.x = k0 * lf  + k1 * c.x + k2 * c.y;
        t.y = k0 * c.x + k1 * c.y + k2 * c.z;
        t.z = k0 * c.y + k1 * c.z + k2 * c.w;
        t.w = k0 * c.z + k1 * c.w + k2 * rt;
        *(float4*)(t_s + r * VOXT + q * 4) = t;
    }
    __syncthreads();

    // stage 2: GEMM out[64][128] = W^T (53x64) * t (53x128)
    const int j0 = (tid & 7) * 8;
    const int v0 = (tid >> 3) * 8;

    unsigned long long acc[8][4];
#pragma unroll
    for (int i = 0; i < 8; i++)
#pragma unroll
        for (int k = 0; k < 4; k++) acc[i][k] = 0ull;

#pragma unroll 2
    for (int r = 0; r < RANK; r++) {
        ulonglong2 wv0 = *(const ulonglong2*)(w_s + r * 64 + j0);
        ulonglong2 wv1 = *(const ulonglong2*)(w_s + r * 64 + j0 + 2);
        ulonglong2 wv2 = *(const ulonglong2*)(w_s + r * 64 + j0 + 4);
        ulonglong2 wv3 = *(const ulonglong2*)(w_s + r * 64 + j0 + 6);
        ulonglong2 ta  = *(const ulonglong2*)(t_s + r * VOXT + v0);
        ulonglong2 tb  = *(const ulonglong2*)(t_s + r * VOXT + v0 + 4);
        unsigned long long w[8] = {wv0.x, wv0.y, wv1.x, wv1.y, wv2.x, wv2.y, wv3.x, wv3.y};
        unsigned long long tt[4] = {ta.x, ta.y, tb.x, tb.y};
#pragma unroll
        for (int i = 0; i < 8; i++)
#pragma unroll
            for (int k = 0; k < 4; k++)
                acc[i][k] = fma2(w[i], tt[k], acc[i][k]);
    }

    const unsigned long long one2 = pk2(1.f, 1.f);
#pragma unroll
    for (int i = 0; i < 8; i++) {
        int j = j0 + i;
        unsigned long long bb = pk2(b_s[j], b_s[j]);
#pragma unroll
        for (int k = 0; k < 4; k++) acc[i][k] = fma2(bb, one2, acc[i][k]);
        float* o = out + (size_t)j * NVOX + vbase + v0;
        *(ulonglong2*)(o)     = make_ulonglong2(acc[i][0], acc[i][1]);
        *(ulonglong2*)(o + 4) = make_ulonglong2(acc[i][2], acc[i][3]);
    }
}

extern "C" void kernel_launch(void* const* d_in, const int* in_sizes, int n_in,
                              void* d_out, int out_size) {
    const float* x     = (const float*)d_in[0];
    const float* Ukh   = (const float*)d_in[1];
    const float* Ukw   = (const float*)d_in[2];
    const float* Ukd   = (const float*)d_in[3];
    const float* Ucin  = (const float*)d_in[4];
    const float* Ucout = (const float*)d_in[5];
    const float* bias  = (const float*)d_in[6];
    float* out = (float*)d_out;

    float *bufA, *bufB;
    cudaGetSymbolAddress((void**)&bufA, g_bufA);
    cudaGetSymbolAddress((void**)&bufB, g_bufB);

    cudaFuncSetAttribute(k_dproj, cudaFuncAttributeMaxDynamicSharedMemorySize, DPROJ_SMEM);

    const int gemm_blocks = NVOX / VOXT;   // 1372

    // 1) pointwise Cin->R into bufA
    k_pointwise<<<gemm_blocks, 128>>>(x, Ucin);
    // 2) fused conv along H and W: bufA -> bufB
    dim3 g2(DIM / TW, DIM / TH, RANK);     // 7 x 7 x 53
    k_convHW<<<g2, 128>>>(bufA, bufB, Ukh, Ukw);
    // 3) depth conv + projection + bias: bufB -> out
    k_dproj<<<gemm_blocks, 128, DPROJ_SMEM>>>(bufB, Ukd, Ucout, bias, out);
}

// round 4
// speedup vs baseline: 2.0717x; 2.0717x over previous
#include <cuda_runtime.h>

#define RANK 53
#define RPAD 56           // rank padded to 7 warps * 8
#define CIN  32
#define COUT 64
#define DIM  56
#define NVOX (56*56*56)   // 175616
#define STRH (56*56)
#define STRW 56
#define TH 8
#define TW 8
#define VOXT 128          // voxels per GEMM tile (NVOX/VOXT = 1372 exact)

// Scratch: two rank-major intermediates [RANK][NVOX] (~35.5 MB each).
__device__ float g_bufA[RANK * NVOX];
__device__ float g_bufB[RANK * NVOX];

// ---------- packed f32x2 helpers (sm_103a) ----------
__device__ __forceinline__ unsigned long long pk2(float lo, float hi) {
    unsigned long long r;
    asm("mov.b64 %0, {%1, %2};" : "=l"(r) : "f"(lo), "f"(hi));
    return r;
}
__device__ __forceinline__ unsigned long long fma2(unsigned long long a,
                                                   unsigned long long b,
                                                   unsigned long long c) {
    unsigned long long d;
    asm("fma.rn.f32x2 %0, %1, %2, %3;" : "=l"(d) : "l"(a), "l"(b), "l"(c));
    return d;
}

// ---------- Kernel 1: pointwise Cin -> RANK ----------
// Warp w computes ranks [8w, 8w+8) for all 128 voxels; lane owns 4 voxels.
// Weight LDS are warp-uniform broadcasts; data LDS lane-contiguous. No conflicts.
__global__ __launch_bounds__(224, 4)
void k_pointwise(const float* __restrict__ x, const float* __restrict__ Ucin) {
    __shared__ float x_s[CIN * VOXT];                    // 16 KB
    __shared__ unsigned long long w_s[CIN * RPAD];       // 14 KB

    const int tid = threadIdx.x;
    const int vbase = blockIdx.x * VOXT;

    for (int i = tid; i < CIN * RPAD; i += 224) {
        int c = i / RPAD, r = i % RPAD;
        float v = (r < RANK) ? Ucin[c * RANK + r] : 0.f;
        w_s[i] = pk2(v, v);
    }
    for (int i = tid; i < CIN * (VOXT / 4); i += 224) {
        int c = i >> 5, q = i & 31;
        *(float4*)(x_s + c * VOXT + q * 4) =
            *(const float4*)(x + (size_t)c * NVOX + vbase + q * 4);
    }
    __syncthreads();

    const int warp = tid >> 5;
    const int lane = tid & 31;
    const int r0 = warp * 8;
    const int v0 = lane * 4;

    unsigned long long acc[8][2];
#pragma unroll
    for (int i = 0; i < 8; i++) { acc[i][0] = 0ull; acc[i][1] = 0ull; }

#pragma unroll 4
    for (int c = 0; c < CIN; c++) {
        const unsigned long long* wp = w_s + c * RPAD + r0;
        ulonglong2 w01 = *(const ulonglong2*)(wp);
        ulonglong2 w23 = *(const ulonglong2*)(wp + 2);
        ulonglong2 w45 = *(const ulonglong2*)(wp + 4);
        ulonglong2 w67 = *(const ulonglong2*)(wp + 6);
        ulonglong2 xv  = *(const ulonglong2*)(x_s + c * VOXT + v0);
        unsigned long long w[8] = {w01.x, w01.y, w23.x, w23.y, w45.x, w45.y, w67.x, w67.y};
#pragma unroll
        for (int i = 0; i < 8; i++) {
            acc[i][0] = fma2(w[i], xv.x, acc[i][0]);
            acc[i][1] = fma2(w[i], xv.y, acc[i][1]);
        }
    }

#pragma unroll
    for (int i = 0; i < 8; i++) {
        int r = r0 + i;
        if (r < RANK)
            *(ulonglong2*)(g_bufA + (size_t)r * NVOX + vbase + v0) =
                make_ulonglong2(acc[i][0], acc[i][1]);
    }
}

// ---------- Kernel 2: fused H+W 3-tap separable conv, smem tiled ----------
__global__ __launch_bounds__(128)
void k_convHW(const float* __restrict__ in, float* __restrict__ out,
              const float* __restrict__ Ukh, const float* __restrict__ Ukw) {
    __shared__ float s[(TH + 2) * (TW + 2) * DIM];   // 22.4 KB

    int r  = blockIdx.z;
    int h0 = blockIdx.y * TH;
    int w0 = blockIdx.x * TW;
    const float* base = in + (size_t)r * NVOX;

    const int NLOAD4 = (TH + 2) * (TW + 2) * (DIM / 4);
    for (int i = threadIdx.x; i < NLOAD4; i += 128) {
        int dq = i % (DIM / 4);
        int t  = i / (DIM / 4);
        int lw = t % (TW + 2);
        int lh = t / (TW + 2);
        int gh = h0 + lh - 1, gw = w0 + lw - 1;
        float4 val = make_float4(0.f, 0.f, 0.f, 0.f);
        if (gh >= 0 && gh < DIM && gw >= 0 && gw < DIM)
            val = *(const float4*)(base + gh * STRH + gw * STRW + dq * 4);
        *(float4*)(s + (lh * (TW + 2) + lw) * DIM + dq * 4) = val;
    }
    __syncthreads();

    float kh[3] = {Ukh[r], Ukh[RANK + r], Ukh[2 * RANK + r]};
    float kw[3] = {Ukw[r], Ukw[RANK + r], Ukw[2 * RANK + r]};
    float kk[9];
#pragma unroll
    for (int i = 0; i < 3; i++)
#pragma unroll
        for (int j = 0; j < 3; j++) kk[i * 3 + j] = kh[i] * kw[j];

    float* obase = out + (size_t)r * NVOX;
    const int NOUT4 = TH * TW * (DIM / 4);
    for (int o = threadIdx.x; o < NOUT4; o += 128) {
        int dq = o % (DIM / 4);
        int t  = o / (DIM / 4);
        int lw = t % TW;
        int lh = t / TW;
        float4 acc = make_float4(0.f, 0.f, 0.f, 0.f);
#pragma unroll
        for (int i = 0; i < 3; i++)
#pragma unroll
            for (int j = 0; j < 3; j++) {
                const float4 v = *(const float4*)(s + ((lh + i) * (TW + 2) + (lw + j)) * DIM + dq * 4);
                float c = kk[i * 3 + j];
                acc.x += c * v.x; acc.y += c * v.y;
                acc.z += c * v.z; acc.w += c * v.w;
            }
        *(float4*)(obase + (h0 + lh) * STRH + (w0 + lw) * STRW + dq * 4) = acc;
    }
}

// ---------- Kernel 3: depth conv + projection RANK -> 64 + bias ----------
// Dynamic smem layout (bytes):
//   t_s  float[53][128]   [0, 27136)
//   w_s  u64  [53][64]    [27136, 54272)
//   kd_s float[3][53]     [54272, 54908)
//   b_s  float[64]        [54908, 55164)
#define DPROJ_SMEM 55168
__global__ __launch_bounds__(256, 3)
void k_dproj(const float* __restrict__ in, const float* __restrict__ Ukd,
             const float* __restrict__ Ucout, const float* __restrict__ bias,
             float* __restrict__ out) {
    extern __shared__ char dsm[];
    float* t_s = (float*)dsm;
    unsigned long long* w_s = (unsigned long long*)(dsm + 27136);
    float* kd_s = (float*)(dsm + 54272);
    float* b_s  = (float*)(dsm + 54908);

    const int tid = threadIdx.x;
    const int vbase = blockIdx.x * VOXT;

    for (int i = tid; i < RANK * COUT; i += 256) {
        float v = Ucout[i];
        w_s[i] = pk2(v, v);
    }
    for (int i = tid; i < 3 * RANK; i += 256) kd_s[i] = Ukd[i];
    if (tid < COUT) b_s[tid] = bias[tid];
    __syncthreads();                       // <-- kd_s must be visible (R3 race fix)

    // stage 1: depth conv -> t_s[r][0..127]
    for (int i = tid; i < RANK * (VOXT / 4); i += 256) {
        int r = i >> 5, q = i & 31;
        int v4 = vbase + q * 4;
        int z  = v4 % DIM;                 // multiple of 4
        const float* p = in + (size_t)r * NVOX + v4;
        float4 c = *(const float4*)p;
        float lf = (z > 0)  ? p[-1] : 0.f;
        float rt = (z < 52) ? p[4]  : 0.f;
        float k0 = kd_s[r], k1 = kd_s[RANK + r], k2 = kd_s[2 * RANK + r];
        float4 t;
        t.x = k0 * lf  + k1 * c.x + k2 * c.y;
        t.y = k0 * c.x + k1 * c.y + k2 * c.z;
        t.z = k0 * c.y + k1 * c.z + k2 * c.w;
        t.w = k0 * c.z + k1 * c.w + k2 * rt;
        *(float4*)(t_s + r * VOXT + q * 4) = t;
    }
    __syncthreads();

    // stage 2: warp w -> couts [8w, 8w+8); lane -> 4 voxels.
    const int warp = tid >> 5;
    const int lane = tid & 31;
    const int j0 = warp * 8;
    const int v0 = lane * 4;

    unsigned long long acc[8][2];
#pragma unroll
    for (int i = 0; i < 8; i++) { acc[i][0] = 0ull; acc[i][1] = 0ull; }

#pragma unroll 4
    for (int r = 0; r < RANK; r++) {
        const unsigned long long* wp = w_s + r * COUT + j0;
        ulonglong2 w01 = *(const ulonglong2*)(wp);
        ulonglong2 w23 = *(const ulonglong2*)(wp + 2);
        ulonglong2 w45 = *(const ulonglong2*)(wp + 4);
        ulonglong2 w67 = *(const ulonglong2*)(wp + 6);
        ulonglong2 tv  = *(const ulonglong2*)(t_s + r * VOXT + v0);
        unsigned long long w[8] = {w01.x, w01.y, w23.x, w23.y, w45.x, w45.y, w67.x, w67.y};
#pragma unroll
        for (int i = 0; i < 8; i++) {
            acc[i][0] = fma2(w[i], tv.x, acc[i][0]);
            acc[i][1] = fma2(w[i], tv.y, acc[i][1]);
        }
    }

    const unsigned long long one2 = pk2(1.f, 1.f);
#pragma unroll
    for (int i = 0; i < 8; i++) {
        int j = j0 + i;
        unsigned long long bb = pk2(b_s[j], b_s[j]);
        acc[i][0] = fma2(bb, one2, acc[i][0]);
        acc[i][1] = fma2(bb, one2, acc[i][1]);
        *(ulonglong2*)(out + (size_t)j * NVOX + vbase + v0) =
            make_ulonglong2(acc[i][0], acc[i][1]);
    }
}

extern "C" void kernel_launch(void* const* d_in, const int* in_sizes, int n_in,
                              void* d_out, int out_size) {
    const float* x     = (const float*)d_in[0];
    const float* Ukh   = (const float*)d_in[1];
    const float* Ukw   = (const float*)d_in[2];
    const float* Ukd   = (const float*)d_in[3];
    const float* Ucin  = (const float*)d_in[4];
    const float* Ucout = (const float*)d_in[5];
    const float* bias  = (const float*)d_in[6];
    float* out = (float*)d_out;

    float *bufA, *bufB;
    cudaGetSymbolAddress((void**)&bufA, g_bufA);
    cudaGetSymbolAddress((void**)&bufB, g_bufB);

    cudaFuncSetAttribute(k_dproj, cudaFuncAttributeMaxDynamicSharedMemorySize, DPROJ_SMEM);

    const int gemm_blocks = NVOX / VOXT;   // 1372

    k_pointwise<<<gemm_blocks, 224>>>(x, Ucin);
    dim3 g2(DIM / TW, DIM / TH, RANK);     // 7 x 7 x 53
    k_convHW<<<g2, 128>>>(bufA, bufB, Ukh, Ukw);
    k_dproj<<<gemm_blocks, 256, DPROJ_SMEM>>>(bufB, Ukd, Ucout, bias, out);
}